// round 1
// baseline (speedup 1.0000x reference)
#include <cuda_runtime.h>
#include <cstdint>

#define SEQ 2048
#define DK  128

// ---------------- static device scratch (no allocations allowed) ------------
__device__ float  g_Pqk[(size_t)SEQ * SEQ];   // P_qk[i][l] = q_i . k_l
__device__ float  g_Pvv[(size_t)SEQ * SEQ];   // P_vv[i][l] = v_i . v_l
__device__ float  g_U[(size_t)SEQ * DK];      // u_l = Sqq_l k_l
__device__ float4 g_scal[SEQ];                // {s_l, k^T Sqq k, v.v, 0}

// ---------------- f32x2 packed helpers (sm_103a) ----------------------------
__device__ __forceinline__ unsigned long long ffma2(unsigned long long a,
                                                    unsigned long long b,
                                                    unsigned long long c) {
    unsigned long long d;
    asm("fma.rn.f32x2 %0, %1, %2, %3;" : "=l"(d) : "l"(a), "l"(b), "l"(c));
    return d;
}
__device__ __forceinline__ unsigned long long fmul2(unsigned long long a,
                                                    unsigned long long b) {
    unsigned long long d;
    asm("mul.rn.f32x2 %0, %1, %2;" : "=l"(d) : "l"(a), "l"(b));
    return d;
}
__device__ __forceinline__ unsigned long long pk2(float lo, float hi) {
    unsigned long long r;
    asm("mov.b64 %0, {%1, %2};" : "=l"(r) : "f"(lo), "f"(hi));
    return r;
}
__device__ __forceinline__ float2 upk2(unsigned long long a) {
    float2 f;
    asm("mov.b64 {%0, %1}, %2;" : "=f"(f.x), "=f"(f.y) : "l"(a));
    return f;
}

// ---------------- Phase 1a: C[i][l] = dot(A_i, B_l), 2048x2048 --------------
// which==0 -> g_Pqk, which==1 -> g_Pvv.  Only tiles with i-block <= l-block
// are needed (consumers mask i<=l), so skip lower-left tiles.
__global__ void __launch_bounds__(256) k_gemm(const float* __restrict__ A,
                                              const float* __restrict__ B,
                                              int which) {
    if (blockIdx.y > blockIdx.x) return;   // causal: only i0 <= l0+63 needed
    float* C = which ? g_Pvv : g_Pqk;
    __shared__ float As[64][33];
    __shared__ float Bs[64][33];
    const int tx = threadIdx.x & 15, ty = threadIdx.x >> 4;
    const int i0 = blockIdx.y * 64, l0 = blockIdx.x * 64;
    float acc[4][4] = {};
    for (int k0 = 0; k0 < DK; k0 += 32) {
        const int t = threadIdx.x;
        const int r = t >> 2, c = (t & 3) * 8;
        float4 a0 = *(const float4*)&A[(size_t)(i0 + r) * DK + k0 + c];
        float4 a1 = *(const float4*)&A[(size_t)(i0 + r) * DK + k0 + c + 4];
        float4 b0 = *(const float4*)&B[(size_t)(l0 + r) * DK + k0 + c];
        float4 b1 = *(const float4*)&B[(size_t)(l0 + r) * DK + k0 + c + 4];
        __syncthreads();
        As[r][c + 0] = a0.x; As[r][c + 1] = a0.y; As[r][c + 2] = a0.z; As[r][c + 3] = a0.w;
        As[r][c + 4] = a1.x; As[r][c + 5] = a1.y; As[r][c + 6] = a1.z; As[r][c + 7] = a1.w;
        Bs[r][c + 0] = b0.x; Bs[r][c + 1] = b0.y; Bs[r][c + 2] = b0.z; Bs[r][c + 3] = b0.w;
        Bs[r][c + 4] = b1.x; Bs[r][c + 5] = b1.y; Bs[r][c + 6] = b1.z; Bs[r][c + 7] = b1.w;
        __syncthreads();
#pragma unroll
        for (int kk = 0; kk < 32; kk++) {
            float a[4], b[4];
#pragma unroll
            for (int i = 0; i < 4; i++) a[i] = As[ty * 4 + i][kk];
#pragma unroll
            for (int j = 0; j < 4; j++) b[j] = Bs[tx * 4 + j][kk];
#pragma unroll
            for (int i = 0; i < 4; i++)
#pragma unroll
                for (int j = 0; j < 4; j++) acc[i][j] += a[i] * b[j];
        }
    }
#pragma unroll
    for (int i = 0; i < 4; i++)
#pragma unroll
        for (int j = 0; j < 4; j++)
            C[(size_t)(i0 + ty * 4 + i) * SEQ + l0 + tx * 4 + j] = acc[i][j];
}

// ---------------- Phase 1b: U[l][d] = (1/l) sum_{i<=l} Pqk[i][l] * Q[i][d] --
// 256 blocks, each handles 8 consecutive l.  256 threads: d = tid&127,
// jh = tid>>7 selects which 4 of the 8 l-columns this thread accumulates.
__global__ void __launch_bounds__(256) k_U(const float* __restrict__ Q) {
    __shared__ float sh[128][8];
    const int tid = threadIdx.x;
    const int d = tid & 127, jh = tid >> 7;
    const int l0 = blockIdx.x * 8;
    float acc[4] = {0.f, 0.f, 0.f, 0.f};
    for (int i0 = 0; i0 <= l0 + 7; i0 += 128) {
        const int r = tid >> 1, c4 = (tid & 1) * 4;
        const int irow = i0 + r;
        float4 pv = *(const float4*)&g_Pqk[(size_t)irow * SEQ + l0 + c4];
        if (irow > l0 + c4 + 0) pv.x = 0.f;
        if (irow > l0 + c4 + 1) pv.y = 0.f;
        if (irow > l0 + c4 + 2) pv.z = 0.f;
        if (irow > l0 + c4 + 3) pv.w = 0.f;
        __syncthreads();
        *(float4*)&sh[r][c4] = pv;
        __syncthreads();
#pragma unroll 8
        for (int r2 = 0; r2 < 128; r2++) {
            float qv = Q[(size_t)(i0 + r2) * DK + d];
            float4 s4 = *(const float4*)&sh[r2][jh * 4];
            acc[0] += qv * s4.x; acc[1] += qv * s4.y;
            acc[2] += qv * s4.z; acc[3] += qv * s4.w;
        }
    }
#pragma unroll
    for (int jl = 0; jl < 4; jl++) {
        const int l = l0 + jh * 4 + jl;
        g_U[(size_t)l * DK + d] = acc[jl] / (float)(l + 1);
    }
}

// ---------------- Phase 1c: per-step scalars --------------------------------
// s_l = (1/l) sum_{i<=l} Pqk*Pvv ; kqq = (1/l) sum Pqk^2 ; vv = Pvv[l][l]
__global__ void __launch_bounds__(256) k_scal() {
    const int tid = threadIdx.x;
    const int lj = tid & 31, grp = tid >> 5;
    const int l = blockIdx.x * 32 + lj;
    float ss = 0.f, k2 = 0.f;
    for (int i = grp; i <= l; i += 8) {
        float pq = g_Pqk[(size_t)i * SEQ + l];
        float pv = g_Pvv[(size_t)i * SEQ + l];
        ss += pq * pv;
        k2 += pq * pq;
    }
    __shared__ float rs[8][32], rk[8][32];
    rs[grp][lj] = ss;
    rk[grp][lj] = k2;
    __syncthreads();
    if (tid < 32) {
        float s = 0.f, kk2 = 0.f;
#pragma unroll
        for (int g = 0; g < 8; g++) { s += rs[g][tid]; kk2 += rk[g][tid]; }
        const int ll = blockIdx.x * 32 + tid;
        const float fl = (float)(ll + 1);
        const float vv = g_Pvv[(size_t)ll * SEQ + ll];
        g_scal[ll] = make_float4(s / fl, kk2 / fl, vv, 0.f);
    }
}

// ---------------- Phase 2: sequential J recursion (single block) ------------
// 512 threads: seg = tid>>7 (0..3 column-segments), row = tid&127.
// J[row][seg*32 .. +32) lives packed in registers (16 x f32x2 per thread).
__global__ void __launch_bounds__(512) k_seq(const float* __restrict__ q,
                                             const float* __restrict__ kg,
                                             const float* __restrict__ v,
                                             float* __restrict__ out) {
    __shared__ float  qsh[2][128], ksh[2][128], vsh[2][128], ush[2][128];
    __shared__ float2 part[512];
    __shared__ float4 wsum[4];
    __shared__ float4 scalsh[2];

    const int tid = threadIdx.x;
    const int seg = tid >> 7;
    const int row = tid & 127;
    const int lane = tid & 127;

    unsigned long long Jp[16];
#pragma unroll
    for (int c = 0; c < 16; c++) Jp[c] = 0ull;
    float S = 0.f, T = 0.f, trS = 0.f;

    // prologue: stage step-0 vectors
    if (seg == 0)      qsh[0][lane] = q[lane];
    else if (seg == 1) ksh[0][lane] = kg[lane];
    else if (seg == 2) vsh[0][lane] = v[lane];
    else               ush[0][lane] = g_U[lane];
    if (tid == 0) scalsh[0] = g_scal[0];
    __syncthreads();

    for (int l = 0; l < SEQ; l++) {
        const int b = l & 1;

        // prefetch step l+1 (one element per thread, hides L2 latency)
        float  nx  = 0.f;
        float4 nsc = make_float4(0.f, 0.f, 0.f, 0.f);
        if (l + 1 < SEQ) {
            const float* src = (seg == 0) ? q : (seg == 1) ? kg
                              : (seg == 2) ? v : g_U;
            nx = src[(size_t)(l + 1) * DK + lane];
            if (tid == 0) nsc = g_scal[l + 1];
        }

        // --- phase A: two packed matvecs: p1 = (J q)|seg , p2 = (J u)|seg ---
        float p1, p2;
        {
            unsigned long long a1 = 0ull, a2 = 0ull;
            const ulonglong2* qp = (const ulonglong2*)&qsh[b][seg * 32];
            const ulonglong2* up = (const ulonglong2*)&ush[b][seg * 32];
#pragma unroll
            for (int c = 0; c < 8; c++) {
                ulonglong2 qv = qp[c];
                ulonglong2 uv = up[c];
                a1 = ffma2(Jp[2 * c + 0], qv.x, a1);
                a1 = ffma2(Jp[2 * c + 1], qv.y, a1);
                a2 = ffma2(Jp[2 * c + 0], uv.x, a2);
                a2 = ffma2(Jp[2 * c + 1], uv.y, a2);
            }
            float2 f1 = upk2(a1), f2 = upk2(a2);
            p1 = f1.x + f1.y;
            p2 = f2.x + f2.y;
        }
        part[tid] = make_float2(p1, p2);
        __syncthreads();

        // --- phase C: per-row combine + block reduce of 3 scalars -----------
        if (tid < 128) {
            float a  = part[tid].x + part[tid + 128].x + part[tid + 256].x + part[tid + 384].x;
            float bb = part[tid].y + part[tid + 128].y + part[tid + 256].y + part[tid + 384].y;
            float vr = vsh[b][tid];
            float x1 = vr * a;    // v . (Jq)
            float x2 = a * a;     // ||Jq||^2
            float x3 = vr * bb;   // v . (Ju)
#pragma unroll
            for (int o = 16; o > 0; o >>= 1) {
                x1 += __shfl_down_sync(0xffffffffu, x1, o);
                x2 += __shfl_down_sync(0xffffffffu, x2, o);
                x3 += __shfl_down_sync(0xffffffffu, x3, o);
            }
            if ((tid & 31) == 0) wsum[tid >> 5] = make_float4(x1, x2, x3, 0.f);
        }
        __syncthreads();

        // --- phase D: scalar logic (redundant in all threads) + J update ----
        float4 w0 = wsum[0], w1 = wsum[1], w2 = wsum[2], w3 = wsum[3];
        const float vJq = w0.x + w1.x + w2.x + w3.x;
        const float aa  = w0.y + w1.y + w2.y + w3.y;
        const float vJu = w0.z + w1.z + w2.z + w3.z;
        const float4 sc = scalsh[b];

        const float fl = (float)(l + 1);
        const float am = (fl - 1.0f) / fl;
        const float bm = 1.0f / fl;

        trS = am * trS + sc.z * bm;
        const float sJ   = am * S + bm * vJq;
        const float A_JJ = am * T + bm * aa;
        const float A_Jl = vJu;
        const float A_ll = sc.z * sc.y;
        const float s_l  = sc.x;

        const bool first = (l == 0);
        const float A_JJ_s = (first || A_JJ == 0.f) ? 1.f : A_JJ;
        const float A_ll_s = (first || A_ll == 0.f) ? 1.f : A_ll;
        const float denom  = A_JJ * A_ll - A_Jl * A_Jl;
        const float denom_s = (first || denom == 0.f) ? 1.f : denom;

        const float margin = s_l - A_Jl * (sJ / A_JJ_s);
        const float rden   = 1.0f / denom_s;
        const float wf = (A_ll * sJ - A_Jl * s_l) * rden;
        const float wi = (A_JJ * s_l - A_Jl * sJ) * rden;
        const float wf_c = (wi <= 0.f) ? (sJ / A_JJ_s) : ((wf <= 0.f) ? 0.f : wf);
        const float wi_c = (wi <= 0.f) ? 0.f : ((wf <= 0.f) ? (s_l / A_ll_s) : wi);
        const bool do_upd = margin > 0.f;

        float cf, ci, upd;
        if (first) {
            cf = 0.f; ci = 1.f; upd = 1.f;
            S = s_l;
            T = A_ll;
        } else if (do_upd) {
            cf = wf_c; ci = wi_c; upd = 1.f;
            S = wf_c * sJ + wi_c * s_l;
            T = wf_c * wf_c * A_JJ + 2.f * wf_c * wi_c * A_Jl + wi_c * wi_c * A_ll;
        } else {
            cf = 1.f; ci = 0.f; upd = 0.f;
            S = sJ;
            T = A_JJ;
        }
        const float cost = 0.5f * trS - S + 0.5f * T;
        if (tid == 0) {
            out[l] = cost;
            out[SEQ + l] = upd;
        }

        // J update (uniform branch)
        if (ci != 0.f || cf != 1.f) {
            const float civ = ci * vsh[b][row];
            const unsigned long long cfp  = pk2(cf, cf);
            const unsigned long long civp = pk2(civ, civ);
            const ulonglong2* kp = (const ulonglong2*)&ksh[b][seg * 32];
#pragma unroll
            for (int c = 0; c < 8; c++) {
                ulonglong2 kv = kp[c];
                Jp[2 * c + 0] = ffma2(Jp[2 * c + 0], cfp, fmul2(civp, kv.x));
                Jp[2 * c + 1] = ffma2(Jp[2 * c + 1], cfp, fmul2(civp, kv.y));
            }
        }

        // stage next-step vectors into the other buffer
        if (l + 1 < SEQ) {
            const int nb = 1 - b;
            if (seg == 0)      qsh[nb][lane] = nx;
            else if (seg == 1) ksh[nb][lane] = nx;
            else if (seg == 2) vsh[nb][lane] = nx;
            else               ush[nb][lane] = nx;
            if (tid == 0) scalsh[nb] = nsc;
        }
        __syncthreads();
    }

    // final J: out[2*SEQ + row*128 + col]
#pragma unroll
    for (int c = 0; c < 16; c++) {
        float2 jf = upk2(Jp[c]);
        out[2 * SEQ + (size_t)row * DK + seg * 32 + 2 * c + 0] = jf.x;
        out[2 * SEQ + (size_t)row * DK + seg * 32 + 2 * c + 1] = jf.y;
    }
}

// ---------------------------------------------------------------------------
extern "C" void kernel_launch(void* const* d_in, const int* in_sizes, int n_in,
                              void* d_out, int out_size) {
    const float* q = (const float*)d_in[0];
    const float* k = (const float*)d_in[1];
    const float* v = (const float*)d_in[2];
    float* out = (float*)d_out;

    dim3 gg(SEQ / 64, SEQ / 64);
    k_gemm<<<gg, 256>>>(q, k, 0);   // P_qk
    k_gemm<<<gg, 256>>>(v, v, 1);   // P_vv
    k_U<<<SEQ / 8, 256>>>(q);
    k_scal<<<SEQ / 32, 256>>>();
    k_seq<<<1, 512>>>(q, k, v, out);
    (void)in_sizes; (void)n_in; (void)out_size;
}